// round 9
// baseline (speedup 1.0000x reference)
#include <cuda_runtime.h>
#include <cuda_fp16.h>
#include <cstdint>
#include <cstddef>

#define BATCH 32
#define SEQ   2048
#define DIM   128
#define QT    64
#define KT    32
#define NT    256
#define HYST  6.0f

// smem: Q hi/lo 16KB each; K stages (hi 8KB + lo 8KB) x2; P x2; m; l
#define QH_OFF 0
#define QL_OFF 16384
#define KH_OFF(s) (32768 + (s)*16384)
#define KL_OFF(s) (40960 + (s)*16384)
#define P_OFF(pb) (65536 + (pb)*5120)   // 64 rows x 80B (fp16, padded stride)
#define M_OFF  75776                     // float[2][64]
#define L_OFF  76288                     // float[2][64]
static constexpr int SMEM_BYTES = 76800;

// pre-split fp16 hi/lo copies (u32 = packed half2), [b][seq][d]
#define NPAIR (BATCH*SEQ*DIM/2)
__device__ uint32_t qh_g[NPAIR];
__device__ uint32_t ql_g[NPAIR];
__device__ uint32_t kh_g[NPAIR];
__device__ uint32_t kl_g[NPAIR];

#define MMA(C, A0, A1, A2, A3, B0, B1)                                  \
    asm volatile("mma.sync.aligned.m16n8k16.row.col.f32.f16.f16.f32 "   \
        "{%0,%1,%2,%3}, {%4,%5,%6,%7}, {%8,%9}, {%0,%1,%2,%3};"         \
        : "+f"(C[0]), "+f"(C[1]), "+f"(C[2]), "+f"(C[3])                \
        : "r"(A0), "r"(A1), "r"(A2), "r"(A3), "r"(B0), "r"(B1))

__device__ __forceinline__ void ldsm4(uint32_t& a, uint32_t& b, uint32_t& c,
                                      uint32_t& d, uint32_t addr)
{
    asm volatile("ldmatrix.sync.aligned.m8n8.x4.shared.b16 {%0,%1,%2,%3},[%4];"
                 : "=r"(a), "=r"(b), "=r"(c), "=r"(d) : "r"(addr));
}
__device__ __forceinline__ void ldsm4t(uint32_t& a, uint32_t& b, uint32_t& c,
                                       uint32_t& d, uint32_t addr)
{
    asm volatile("ldmatrix.sync.aligned.m8n8.x4.trans.shared.b16 {%0,%1,%2,%3},[%4];"
                 : "=r"(a), "=r"(b), "=r"(c), "=r"(d) : "r"(addr));
}
__device__ __forceinline__ void cp16(uint32_t dst, const void* src)
{
    asm volatile("cp.async.cg.shared.global [%0], [%1], 16;" :: "r"(dst), "l"(src));
}
#define CP_COMMIT()  asm volatile("cp.async.commit_group;")
#define CP_WAIT1()   asm volatile("cp.async.wait_group 1;")

__device__ __forceinline__ uint32_t hscale(uint32_t v, float f)
{
    __half2 x = *(__half2*)&v;
    __half2 s = __float2half2_rn(f);
    x = __hmul2(x, s);
    return *(uint32_t*)&x;
}

// split (a,b) fp32 -> packed fp16 hi pair + lo pair (x = hi + lo)
__device__ __forceinline__ void split2(float a, float b, uint32_t& hi, uint32_t& lo)
{
    __half ha = __float2half_rn(a), hb = __float2half_rn(b);
    __half la = __float2half_rn(a - __half2float(ha));
    __half lb = __float2half_rn(b - __half2float(hb));
    __half2 H = __halves2half2(ha, hb);
    __half2 L = __halves2half2(la, lb);
    hi = *(uint32_t*)&H;
    lo = *(uint32_t*)&L;
}

// ---------------------------------------------------------------------------
// JAX threefry-2x32 (partitionable fold), key=(0,42). Verified R1-R8.
// ---------------------------------------------------------------------------
__device__ __forceinline__ uint32_t threefry_bits(uint32_t idx)
{
    uint32_t x0 = 0u;
    uint32_t x1 = idx + 42u;
    const uint32_t ks1 = 42u;
    const uint32_t ks2 = 0x1BD11BDAu ^ 42u;

#define TF_R4(a,b,c,d)                                          \
    x0 += x1; x1 = __funnelshift_l(x1, x1, (a)); x1 ^= x0;      \
    x0 += x1; x1 = __funnelshift_l(x1, x1, (b)); x1 ^= x0;      \
    x0 += x1; x1 = __funnelshift_l(x1, x1, (c)); x1 ^= x0;      \
    x0 += x1; x1 = __funnelshift_l(x1, x1, (d)); x1 ^= x0;

    TF_R4(13,15,26, 6)  x0 += ks1;  x1 += ks2 + 1u;
    TF_R4(17,29,16,24)  x0 += ks2;  x1 += 2u;
    TF_R4(13,15,26, 6)              x1 += ks1 + 3u;
    TF_R4(17,29,16,24)  x0 += ks1;  x1 += ks2 + 4u;
    TF_R4(13,15,26, 6)  x0 += ks2;  x1 += 5u;
#undef TF_R4
    return x0 ^ x1;
}

__global__ void split_kernel(const float2* __restrict__ x1,
                             const float2* __restrict__ x2)
{
    const float SCALE = 3.36358566f;   // 128**0.25 folded into Q
    int i = blockIdx.x * blockDim.x + threadIdx.x;
    float2 q = x1[i];
    float2 k = x2[i];
    uint32_t h, l;
    split2(q.x * SCALE, q.y * SCALE, h, l);
    qh_g[i] = h; ql_g[i] = l;
    split2(k.x, k.y, h, l);
    kh_g[i] = h; kl_g[i] = l;
}

// smem tile: rows x 256B (128 fp16), 16B chunks XOR-swizzled by row&7
template <int CHUNKS>
__device__ __forceinline__ void load_tile(uint32_t dstH, uint32_t dstL,
                                          const char* srcH, const char* srcL,
                                          int tid)
{
#pragma unroll
    for (int j = 0; j < CHUNKS / NT; ++j) {
        const int c   = tid + j * NT;
        const int row = c >> 4, ch = c & 15;
        const uint32_t off = row * 256 + ((ch ^ (row & 7)) << 4);
        cp16(dstH + off, srcH + c * 16);
        cp16(dstL + off, srcL + c * 16);
    }
}

// ---------------------------------------------------------------------------
// Split-warp flash attention: 8 warps, warp (wq, wk).
//  QK/softmax: warp owns q-rows wq*16..+15, k-cols wk*16..+15 of tile;
//    independent hysteresis softmax per column half; P~ (own-m scale) -> smem.
//  PV: warp owns same rows, d-half wk*64..+63, full k=32; P A-frags from smem
//    rescaled by e^{m_half - M} (M = max of halves, tracked exactly).
//  l merged across halves at the end via smem.
// ---------------------------------------------------------------------------
__global__ void __launch_bounds__(NT, 2)
attn_kernel(float* __restrict__ out)
{
    extern __shared__ char smc[];
    const uint32_t smem = (uint32_t)__cvta_generic_to_shared(smc);
    float* sm_m = (float*)(smc + M_OFF);   // [2][64]
    float* sm_l = (float*)(smc + L_OFF);   // [2][64]

    const int b    = blockIdx.y;
    const int qt0  = blockIdx.x * QT;
    const int tid  = threadIdx.x;
    const int w    = tid >> 5;
    const int lane = tid & 31;
    const int wq   = w & 3;
    const int wk   = w >> 2;
    const int g    = lane >> 2;
    const int p    = lane & 3;
    const int lane7 = lane & 7;
    const int sub   = lane >> 3;

    // ldmatrix addressing
    const int rA = lane7 + ((sub & 1) << 3);   // A-frag / trans-B row add
    const int cA = sub >> 1;                   // chunk add
    const int rB = lane7 + ((sub >> 1) << 3);  // B-frag (QK) row add
    const int cB = sub & 1;

    const char* qhb = (const char*)qh_g + (size_t)(b*SEQ + qt0) * 256;
    const char* qlb = (const char*)ql_g + (size_t)(b*SEQ + qt0) * 256;
    const char* khb = (const char*)kh_g + (size_t)b * SEQ * 256;
    const char* klb = (const char*)kl_g + (size_t)b * SEQ * 256;

    load_tile<QT*16>(smem + QH_OFF, smem + QL_OFF, qhb, qlb, tid);
    load_tile<KT*16>(smem + KH_OFF(0), smem + KL_OFF(0), khb, klb, tid);
    CP_COMMIT();
    load_tile<KT*16>(smem + KH_OFF(1), smem + KL_OFF(1), khb + KT*256, klb + KT*256, tid);
    CP_COMMIT();

    float o[8][4];                      // rows (g, g+8) x d-half (32 regs)
    float m0 = -1e30f, m1 = -1e30f;     // own-half running max (rows g, g+8)
    float l0 = 0.f, l1 = 0.f;           // own-half normalizer (own-m scale)
    float M0 = -1e30f, M1 = -1e30f;     // O scale = max of both halves
#pragma unroll
    for (int nt = 0; nt < 8; ++nt)
#pragma unroll
        for (int j = 0; j < 4; ++j) o[nt][j] = 0.f;

    const uint32_t qrow = smem + QH_OFF + (wq*16 + rA) * 256;
    const int rg  = wq*16 + g;          // q row in tile
    const int rg8 = rg + 8;

    for (int t = 0; t < SEQ/KT; ++t) {
        CP_WAIT1();
        __syncthreads();
        const uint32_t kh0 = smem + KH_OFF(t & 1);

        // ---- S = Q K^T (own k-half): 3 products, 2 n8-tiles ----
        float s[2][4];
#pragma unroll
        for (int nt = 0; nt < 2; ++nt)
#pragma unroll
            for (int j = 0; j < 4; ++j) s[nt][j] = 0.f;

#pragma unroll
        for (int kc = 0; kc < 8; ++kc) {
            const uint32_t aoff = ((2*kc + cA) ^ lane7) << 4;
            uint32_t qa0, qa1, qa2, qa3, la0, la1, la2, la3;
            ldsm4(qa0, qa1, qa2, qa3, qrow + aoff);
            ldsm4(la0, la1, la2, la3, qrow + aoff + (QL_OFF - QH_OFF));

            const uint32_t boff = ((2*kc + cB) ^ lane7) << 4;
            const uint32_t baddr = kh0 + (wk*16 + rB) * 256 + boff;
            uint32_t kb0, kb1, kb2, kb3, lb0, lb1, lb2, lb3;
            ldsm4(kb0, kb1, kb2, kb3, baddr);
            ldsm4(lb0, lb1, lb2, lb3, baddr + 8192);
            MMA(s[0], qa0, qa1, qa2, qa3, kb0, kb1);
            MMA(s[1], qa0, qa1, qa2, qa3, kb2, kb3);
            MMA(s[0], la0, la1, la2, la3, kb0, kb1);
            MMA(s[1], la0, la1, la2, la3, kb2, kb3);
            MMA(s[0], qa0, qa1, qa2, qa3, lb0, lb1);
            MMA(s[1], qa0, qa1, qa2, qa3, lb2, lb3);
        }

        // ---- own-half hysteresis max ----
        float mx0 = fmaxf(fmaxf(s[0][0], s[0][1]), fmaxf(s[1][0], s[1][1]));
        float mx1 = fmaxf(fmaxf(s[0][2], s[0][3]), fmaxf(s[1][2], s[1][3]));
        mx0 = fmaxf(mx0, __shfl_xor_sync(0xffffffffu, mx0, 1));
        mx0 = fmaxf(mx0, __shfl_xor_sync(0xffffffffu, mx0, 2));
        mx1 = fmaxf(mx1, __shfl_xor_sync(0xffffffffu, mx1, 1));
        mx1 = fmaxf(mx1, __shfl_xor_sync(0xffffffffu, mx1, 2));
        if (mx0 > m0 + HYST) { l0 *= __expf(m0 - mx0); m0 = mx0; }
        if (mx1 > m1 + HYST) { l1 *= __expf(m1 - mx1); m1 = mx1; }
        if (p == 0) { sm_m[wk*64 + rg] = m0; sm_m[wk*64 + rg8] = m1; }

        // ---- gated exp + threefry dropout; P~ (fp16, own-m) -> smem ----
        const uint32_t rb0 = (uint32_t)(b*SEQ + qt0 + rg) * (uint32_t)SEQ
                           + (uint32_t)(t*KT + wk*16 + 2*p);
        const uint32_t rb1 = rb0 + 8u * (uint32_t)SEQ;
        const uint32_t pst = smem + P_OFF(t & 1) + (uint32_t)(rg*80 + wk*32 + 4*p);
#pragma unroll
        for (int nt = 0; nt < 2; ++nt) {
            float pm[4];
#pragma unroll
            for (int j = 0; j < 4; ++j) {
                const bool hi8 = (j >= 2);
                const float dlt = s[nt][j] - (hi8 ? m1 : m0);
                float v = 0.f;
                if (dlt > -18.42f) {
                    const float e = __expf(dlt);
                    if (hi8) l1 += e; else l0 += e;
                    const uint32_t idx = (hi8 ? rb1 : rb0) + nt*8 + (j & 1);
                    const uint32_t bits = threefry_bits(idx);
                    const float u = __uint_as_float((bits >> 9) | 0x3f800000u) - 1.0f;
                    v = (u < 0.9f) ? e : 0.f;
                }
                pm[j] = v;
            }
            __half2 h01 = __floats2half2_rn(pm[0], pm[1]);
            __half2 h23 = __floats2half2_rn(pm[2], pm[3]);
            asm volatile("st.shared.b32 [%0], %1;" :: "r"(pst + nt*16),
                         "r"(*(uint32_t*)&h01) : "memory");
            asm volatile("st.shared.b32 [%0], %1;" :: "r"(pst + nt*16 + 8*80),
                         "r"(*(uint32_t*)&h23) : "memory");
        }
        __syncthreads();   // P + m ready

        // ---- PV: O(d-half) += P~(full k=32) V ----
        const float ma0 = sm_m[rg],      mb0 = sm_m[64 + rg];
        const float ma1 = sm_m[rg8],     mb1 = sm_m[64 + rg8];
        const float Mx0 = fmaxf(ma0, mb0), Mx1 = fmaxf(ma1, mb1);
        if (Mx0 > M0) {
            const float c = __expf(M0 - Mx0);
#pragma unroll
            for (int nt = 0; nt < 8; ++nt) { o[nt][0] *= c; o[nt][1] *= c; }
            M0 = Mx0;
        }
        if (Mx1 > M1) {
            const float c = __expf(M1 - Mx1);
#pragma unroll
            for (int nt = 0; nt < 8; ++nt) { o[nt][2] *= c; o[nt][3] *= c; }
            M1 = Mx1;
        }
        const float fh0[2] = { __expf(ma0 - M0), __expf(mb0 - M0) };
        const float fh1[2] = { __expf(ma1 - M1), __expf(mb1 - M1) };

#pragma unroll
        for (int kc2 = 0; kc2 < 2; ++kc2) {
            const uint32_t paddr = smem + P_OFF(t & 1)
                                 + (uint32_t)((wq*16 + rA)*80 + kc2*32 + cA*16);
            uint32_t pa0, pa1, pa2, pa3;
            ldsm4(pa0, pa1, pa2, pa3, paddr);
            pa0 = hscale(pa0, fh0[kc2]);  pa2 = hscale(pa2, fh0[kc2]);
            pa1 = hscale(pa1, fh1[kc2]);  pa3 = hscale(pa3, fh1[kc2]);
            const uint32_t trow = kh0 + (kc2*16 + rA) * 256;
#pragma unroll
            for (int dcp = 0; dcp < 4; ++dcp) {
                const uint32_t toff = (((wk<<3) + 2*dcp + cA) ^ lane7) << 4;
                uint32_t vb0, vb1, vb2, vb3;
                ldsm4t(vb0, vb1, vb2, vb3, trow + toff);
                const int nt = dcp * 2;
                MMA(o[nt],   pa0, pa1, pa2, pa3, vb0, vb1);
                MMA(o[nt+1], pa0, pa1, pa2, pa3, vb2, vb3);
            }
        }

        __syncthreads();
        if (t + 2 < SEQ/KT)
            load_tile<KT*16>(smem + KH_OFF(t & 1), smem + KL_OFF(t & 1),
                             khb + (size_t)(t + 2) * KT * 256,
                             klb + (size_t)(t + 2) * KT * 256, tid);
        CP_COMMIT();
    }

    // ---- merge l across halves; output own (rows, d-half) ----
    l0 += __shfl_xor_sync(0xffffffffu, l0, 1);
    l0 += __shfl_xor_sync(0xffffffffu, l0, 2);
    l1 += __shfl_xor_sync(0xffffffffu, l1, 1);
    l1 += __shfl_xor_sync(0xffffffffu, l1, 2);
    if (p == 0) { sm_l[wk*64 + rg] = l0; sm_l[wk*64 + rg8] = l1; }
    __syncthreads();

    const float ma0 = sm_m[rg],  mb0 = sm_m[64 + rg];
    const float ma1 = sm_m[rg8], mb1 = sm_m[64 + rg8];
    const float La0 = sm_l[rg],  Lb0 = sm_l[64 + rg];
    const float La1 = sm_l[rg8], Lb1 = sm_l[64 + rg8];
    const float L0 = La0 * __expf(ma0 - M0) + Lb0 * __expf(mb0 - M0);
    const float L1 = La1 * __expf(ma1 - M1) + Lb1 * __expf(mb1 - M1);
    const float inv0 = 1.0f / (L0 * 0.9f);
    const float inv1 = 1.0f / (L1 * 0.9f);

    float2* op0 = (float2*)(out + (size_t)(b*SEQ + qt0 + rg)  * DIM + wk*64);
    float2* op1 = (float2*)(out + (size_t)(b*SEQ + qt0 + rg8) * DIM + wk*64);
#pragma unroll
    for (int nt = 0; nt < 8; ++nt) {
        float2 v0, v1;
        v0.x = o[nt][0] * inv0; v0.y = o[nt][1] * inv0;
        v1.x = o[nt][2] * inv1; v1.y = o[nt][3] * inv1;
        op0[nt*4 + p] = v0;
        op1[nt*4 + p] = v1;
    }
}

extern "C" void kernel_launch(void* const* d_in, const int* in_sizes, int n_in,
                              void* d_out, int out_size)
{
    (void)in_sizes; (void)n_in; (void)out_size;
    const float2* x1 = (const float2*)d_in[0];
    const float2* x2 = (const float2*)d_in[1];
    float* out = (float*)d_out;

    split_kernel<<<NPAIR / 256, 256>>>(x1, x2);

    cudaFuncSetAttribute(attn_kernel,
                         cudaFuncAttributeMaxDynamicSharedMemorySize, SMEM_BYTES);
    dim3 grid(SEQ / QT, BATCH);
    attn_kernel<<<grid, NT, SMEM_BYTES>>>(out);
}

// round 10
// speedup vs baseline: 1.1573x; 1.1573x over previous
#include <cuda_runtime.h>
#include <cuda_fp16.h>
#include <cstdint>
#include <cstddef>

#define BATCH 32
#define SEQ   2048
#define DIM   128
#define QT    64
#define KT    32
#define NT    128
#define NTILES (SEQ/KT)
#define HYST  6.0f

// smem: Q hi/lo 16KB each; kh x3 stages (8KB), kl x2 stages (8KB)
#define QH_OFF 0
#define QL_OFF 16384
#define KH_OFF(s) (32768 + (s)*8192)   // s in 0..2
#define KL_OFF(s) (57344 + (s)*8192)   // s in 0..1
static constexpr int SMEM_BYTES = 73728;

// pre-split fp16 hi/lo copies (u32 = packed half2), [b][seq][d]
#define NPAIR (BATCH*SEQ*DIM/2)
__device__ uint32_t qh_g[NPAIR];
__device__ uint32_t ql_g[NPAIR];
__device__ uint32_t kh_g[NPAIR];
__device__ uint32_t kl_g[NPAIR];

#define MMA(C, A0, A1, A2, A3, B0, B1)                                  \
    asm volatile("mma.sync.aligned.m16n8k16.row.col.f32.f16.f16.f32 "   \
        "{%0,%1,%2,%3}, {%4,%5,%6,%7}, {%8,%9}, {%0,%1,%2,%3};"         \
        : "+f"(C[0]), "+f"(C[1]), "+f"(C[2]), "+f"(C[3])                \
        : "r"(A0), "r"(A1), "r"(A2), "r"(A3), "r"(B0), "r"(B1))

__device__ __forceinline__ void ldsm4(uint32_t& a, uint32_t& b, uint32_t& c,
                                      uint32_t& d, uint32_t addr)
{
    asm volatile("ldmatrix.sync.aligned.m8n8.x4.shared.b16 {%0,%1,%2,%3},[%4];"
                 : "=r"(a), "=r"(b), "=r"(c), "=r"(d) : "r"(addr));
}
__device__ __forceinline__ void ldsm4t(uint32_t& a, uint32_t& b, uint32_t& c,
                                       uint32_t& d, uint32_t addr)
{
    asm volatile("ldmatrix.sync.aligned.m8n8.x4.trans.shared.b16 {%0,%1,%2,%3},[%4];"
                 : "=r"(a), "=r"(b), "=r"(c), "=r"(d) : "r"(addr));
}
__device__ __forceinline__ void cp16(uint32_t dst, const void* src)
{
    asm volatile("cp.async.cg.shared.global [%0], [%1], 16;" :: "r"(dst), "l"(src));
}
#define CP_COMMIT()  asm volatile("cp.async.commit_group;")
#define CP_WAIT1()   asm volatile("cp.async.wait_group 1;")

// split (a,b) fp32 -> packed fp16 hi pair + lo pair (x = hi + lo)
__device__ __forceinline__ void split2(float a, float b, uint32_t& hi, uint32_t& lo)
{
    __half ha = __float2half_rn(a), hb = __float2half_rn(b);
    __half la = __float2half_rn(a - __half2float(ha));
    __half lb = __float2half_rn(b - __half2float(hb));
    __half2 H = __halves2half2(ha, hb);
    __half2 L = __halves2half2(la, lb);
    hi = *(uint32_t*)&H;
    lo = *(uint32_t*)&L;
}

// ---------------------------------------------------------------------------
// JAX threefry-2x32 (partitionable fold), key=(0,42). Verified R1-R9.
// ---------------------------------------------------------------------------
__device__ __forceinline__ uint32_t threefry_bits(uint32_t idx)
{
    uint32_t x0 = 0u;
    uint32_t x1 = idx + 42u;
    const uint32_t ks1 = 42u;
    const uint32_t ks2 = 0x1BD11BDAu ^ 42u;

#define TF_R4(a,b,c,d)                                          \
    x0 += x1; x1 = __funnelshift_l(x1, x1, (a)); x1 ^= x0;      \
    x0 += x1; x1 = __funnelshift_l(x1, x1, (b)); x1 ^= x0;      \
    x0 += x1; x1 = __funnelshift_l(x1, x1, (c)); x1 ^= x0;      \
    x0 += x1; x1 = __funnelshift_l(x1, x1, (d)); x1 ^= x0;

    TF_R4(13,15,26, 6)  x0 += ks1;  x1 += ks2 + 1u;
    TF_R4(17,29,16,24)  x0 += ks2;  x1 += 2u;
    TF_R4(13,15,26, 6)              x1 += ks1 + 3u;
    TF_R4(17,29,16,24)  x0 += ks1;  x1 += ks2 + 4u;
    TF_R4(13,15,26, 6)  x0 += ks2;  x1 += 5u;
#undef TF_R4
    return x0 ^ x1;
}

__global__ void split_kernel(const float2* __restrict__ x1,
                             const float2* __restrict__ x2)
{
    const float SCALE = 3.36358566f;   // 128**0.25 folded into Q
    int i = blockIdx.x * blockDim.x + threadIdx.x;
    float2 q = x1[i];
    float2 k = x2[i];
    uint32_t h, l;
    split2(q.x * SCALE, q.y * SCALE, h, l);
    qh_g[i] = h; ql_g[i] = l;
    split2(k.x, k.y, h, l);
    kh_g[i] = h; kl_g[i] = l;
}

// smem tile: rows x 256B (128 fp16), 16B chunks XOR-swizzled by row&7
template <int CHUNKS>
__device__ __forceinline__ void load_tile(uint32_t dstH, uint32_t dstL,
                                          const char* srcH, const char* srcL,
                                          int tid)
{
#pragma unroll
    for (int j = 0; j < CHUNKS / NT; ++j) {
        const int c   = tid + j * NT;
        const int row = c >> 4, ch = c & 15;
        const uint32_t off = row * 256 + ((ch ^ (row & 7)) << 4);
        cp16(dstH + off, srcH + c * 16);
        cp16(dstL + off, srcL + c * 16);
    }
}

// ---------------------------------------------------------------------------
// fp16 split flash attention, deferred-PV pipeline. 4 warps, QT=64, KT=32,
// 3 CTAs/SM. Per tile: [sync] QK(t) + PV(t-1) contiguous MMA burst [sync]
// load(t+2), softmax(t). PV skipped for warp-tiles whose entire P~ is gated
// to zero (ballot). QK: 3 products; PV: 1 product (~2e-4 rel err, R8-verified).
// ---------------------------------------------------------------------------
__global__ void __launch_bounds__(NT, 3)
attn_kernel(float* __restrict__ out)
{
    extern __shared__ char smc[];
    const uint32_t smem = (uint32_t)__cvta_generic_to_shared(smc);

    const int b    = blockIdx.y;
    const int qt0  = blockIdx.x * QT;
    const int tid  = threadIdx.x;
    const int w    = tid >> 5;
    const int lane = tid & 31;
    const int g    = lane >> 2;
    const int p    = lane & 3;
    const int lane7 = lane & 7;
    const int sub   = lane >> 3;

    // ldmatrix addressing (row&7 == lane7 for all types):
    const int rA = lane7 + ((sub & 1) << 3);   // A-frag / trans-B row add
    const int cA = sub >> 1;                   // chunk add
    const int rB = lane7 + ((sub >> 1) << 3);  // B-frag (QK) row add
    const int cB = sub & 1;

    const char* qhb = (const char*)qh_g + (size_t)(b*SEQ + qt0) * 256;
    const char* qlb = (const char*)ql_g + (size_t)(b*SEQ + qt0) * 256;
    const char* khb = (const char*)kh_g + (size_t)b * SEQ * 256;
    const char* klb = (const char*)kl_g + (size_t)b * SEQ * 256;

    // prologue: Q + K tiles 0,1
    load_tile<QT*16>(smem + QH_OFF, smem + QL_OFF, qhb, qlb, tid);
    load_tile<KT*16>(smem + KH_OFF(0), smem + KL_OFF(0), khb, klb, tid);
    CP_COMMIT();
    load_tile<KT*16>(smem + KH_OFF(1), smem + KL_OFF(1), khb + KT*256, klb + KT*256, tid);
    CP_COMMIT();

    float o[16][4];
    float m0 = -1e30f, m1 = -1e30f, l0 = 0.f, l1 = 0.f;
#pragma unroll
    for (int nt = 0; nt < 16; ++nt)
#pragma unroll
        for (int j = 0; j < 4; ++j) o[nt][j] = 0.f;

    uint32_t phv[4][2];        // P~ of previous tile (fp16 hi)
    int act_prev = 0;          // previous tile has any nonzero P~

    const uint32_t qrow = smem + QH_OFF + (w*16 + rA) * 256;
    const uint32_t rbase = (uint32_t)(b*SEQ + qt0 + w*16 + g) * (uint32_t)SEQ + 2*p;

    for (int t = 0; t < NTILES; ++t) {
        CP_WAIT1();
        __syncthreads();
        const uint32_t khS = smem + KH_OFF(t % 3);
        const uint32_t klS = smem + KL_OFF(t & 1);

        // ---- S = Q K^T : 3-product fp16 MMA ----
        float s[4][4];
#pragma unroll
        for (int nt = 0; nt < 4; ++nt)
#pragma unroll
            for (int j = 0; j < 4; ++j) s[nt][j] = 0.f;

#pragma unroll
        for (int kc = 0; kc < 8; ++kc) {
            const uint32_t aoff = ((2*kc + cA) ^ lane7) << 4;
            uint32_t qa0, qa1, qa2, qa3, la0, la1, la2, la3;
            ldsm4(qa0, qa1, qa2, qa3, qrow + aoff);
            ldsm4(la0, la1, la2, la3, qrow + aoff + (QL_OFF - QH_OFF));

            const uint32_t boff = ((2*kc + cB) ^ lane7) << 4;
#pragma unroll
            for (int n0g = 0; n0g < 2; ++n0g) {
                const uint32_t rowoff = (n0g*16 + rB) * 256 + boff;
                uint32_t kb0, kb1, kb2, kb3, lb0, lb1, lb2, lb3;
                ldsm4(kb0, kb1, kb2, kb3, khS + rowoff);
                ldsm4(lb0, lb1, lb2, lb3, klS + rowoff);
                const int nt = n0g * 2;
                MMA(s[nt],   qa0, qa1, qa2, qa3, kb0, kb1);
                MMA(s[nt+1], qa0, qa1, qa2, qa3, kb2, kb3);
                MMA(s[nt],   la0, la1, la2, la3, kb0, kb1);
                MMA(s[nt+1], la0, la1, la2, la3, kb2, kb3);
                MMA(s[nt],   qa0, qa1, qa2, qa3, lb0, lb1);
                MMA(s[nt+1], qa0, qa1, qa2, qa3, lb2, lb3);
            }
        }

        // ---- deferred PV(t-1): O += P~ V, V = kh stage (t-1)%3 ----
        if (act_prev) {
            const uint32_t khP = smem + KH_OFF((t + 2) % 3);   // (t-1)%3
#pragma unroll
            for (int kc2 = 0; kc2 < 2; ++kc2) {
                const uint32_t pa0 = phv[2*kc2][0],   pa1 = phv[2*kc2][1];
                const uint32_t pa2 = phv[2*kc2+1][0], pa3 = phv[2*kc2+1][1];
                const uint32_t trow = khP + (kc2*16 + rA) * 256;
#pragma unroll
                for (int dcp = 0; dcp < 8; ++dcp) {
                    const uint32_t toff = ((2*dcp + cA) ^ lane7) << 4;
                    uint32_t vb0, vb1, vb2, vb3;
                    ldsm4t(vb0, vb1, vb2, vb3, trow + toff);
                    const int nt = dcp * 2;
                    MMA(o[nt],   pa0, pa1, pa2, pa3, vb0, vb1);
                    MMA(o[nt+1], pa0, pa1, pa2, pa3, vb2, vb3);
                }
            }
        }

        __syncthreads();   // stage (t+2)%3 / kl (t&1) free for overwrite
        if (t + 2 < NTILES)
            load_tile<KT*16>(smem + KH_OFF((t + 2) % 3), smem + KL_OFF(t & 1),
                             khb + (size_t)(t + 2) * KT * 256,
                             klb + (size_t)(t + 2) * KT * 256, tid);
        CP_COMMIT();

        // ---- softmax(t): hysteresis max, ballot-gated exp/RNG/pack ----
        float mx0 = -1e30f, mx1 = -1e30f;
#pragma unroll
        for (int nt = 0; nt < 4; ++nt) {
            mx0 = fmaxf(mx0, fmaxf(s[nt][0], s[nt][1]));
            mx1 = fmaxf(mx1, fmaxf(s[nt][2], s[nt][3]));
        }
        mx0 = fmaxf(mx0, __shfl_xor_sync(0xffffffffu, mx0, 1));
        mx0 = fmaxf(mx0, __shfl_xor_sync(0xffffffffu, mx0, 2));
        mx1 = fmaxf(mx1, __shfl_xor_sync(0xffffffffu, mx1, 1));
        mx1 = fmaxf(mx1, __shfl_xor_sync(0xffffffffu, mx1, 2));

        float c0 = 1.f, c1 = 1.f;
        int flag = 0;
        if (mx0 > m0 + HYST) { c0 = __expf(m0 - mx0); m0 = mx0; l0 *= c0; flag = 1; }
        if (mx1 > m1 + HYST) { c1 = __expf(m1 - mx1); m1 = mx1; l1 *= c1; flag = 1; }
        if (__ballot_sync(0xffffffffu, flag)) {
#pragma unroll
            for (int nt = 0; nt < 16; ++nt) {
                o[nt][0] *= c0; o[nt][1] *= c0;
                o[nt][2] *= c1; o[nt][3] *= c1;
            }
        }

        // whole warp-tile below the gate? skip exp/RNG/pack + next PV
        const uint32_t actb = __ballot_sync(0xffffffffu,
            (mx0 - m0 > -18.42f) || (mx1 - m1 > -18.42f));
        act_prev = (actb != 0);
        if (act_prev) {
            const uint32_t rb0 = rbase + (uint32_t)(t*KT);
            const uint32_t rb1 = rb0 + 8u * (uint32_t)SEQ;
#pragma unroll
            for (int nt = 0; nt < 4; ++nt) {
                float pm[4];
#pragma unroll
                for (int j = 0; j < 4; ++j) {
                    const bool hi8 = (j >= 2);
                    const float dlt = s[nt][j] - (hi8 ? m1 : m0);
                    float v = 0.f;
                    if (dlt > -18.42f) {
                        const float e = __expf(dlt);
                        if (hi8) l1 += e; else l0 += e;
                        const uint32_t idx = (hi8 ? rb1 : rb0) + nt*8 + (j & 1);
                        const uint32_t bits = threefry_bits(idx);
                        const float u = __uint_as_float((bits >> 9) | 0x3f800000u) - 1.0f;
                        v = (u < 0.9f) ? e : 0.f;
                    }
                    pm[j] = v;
                }
                __half2 h01 = __floats2half2_rn(pm[0], pm[1]);
                __half2 h23 = __floats2half2_rn(pm[2], pm[3]);
                phv[nt][0] = *(uint32_t*)&h01;
                phv[nt][1] = *(uint32_t*)&h23;
            }
        }
    }

    // ---- final PV for tile NTILES-1 (stage (NTILES-1)%3 still intact) ----
    if (act_prev) {
        const uint32_t khP = smem + KH_OFF((NTILES - 1) % 3);
#pragma unroll
        for (int kc2 = 0; kc2 < 2; ++kc2) {
            const uint32_t pa0 = phv[2*kc2][0],   pa1 = phv[2*kc2][1];
            const uint32_t pa2 = phv[2*kc2+1][0], pa3 = phv[2*kc2+1][1];
            const uint32_t trow = khP + (kc2*16 + rA) * 256;
#pragma unroll
            for (int dcp = 0; dcp < 8; ++dcp) {
                const uint32_t toff = ((2*dcp + cA) ^ lane7) << 4;
                uint32_t vb0, vb1, vb2, vb3;
                ldsm4t(vb0, vb1, vb2, vb3, trow + toff);
                const int nt = dcp * 2;
                MMA(o[nt],   pa0, pa1, pa2, pa3, vb0, vb1);
                MMA(o[nt+1], pa0, pa1, pa2, pa3, vb2, vb3);
            }
        }
    }

    // ---- epilogue ----
    l0 += __shfl_xor_sync(0xffffffffu, l0, 1);
    l0 += __shfl_xor_sync(0xffffffffu, l0, 2);
    l1 += __shfl_xor_sync(0xffffffffu, l1, 1);
    l1 += __shfl_xor_sync(0xffffffffu, l1, 2);
    const float inv0 = 1.0f / (l0 * 0.9f);
    const float inv1 = 1.0f / (l1 * 0.9f);

    const int row0 = qt0 + w*16 + g;
    float2* op0 = (float2*)(out + (size_t)(b*SEQ + row0) * DIM);
    float2* op1 = (float2*)(out + (size_t)(b*SEQ + row0 + 8) * DIM);
#pragma unroll
    for (int nt = 0; nt < 16; ++nt) {
        float2 v0, v1;
        v0.x = o[nt][0] * inv0; v0.y = o[nt][1] * inv0;
        v1.x = o[nt][2] * inv1; v1.y = o[nt][3] * inv1;
        op0[nt*4 + p] = v0;
        op1[nt*4 + p] = v1;
    }
}

extern "C" void kernel_launch(void* const* d_in, const int* in_sizes, int n_in,
                              void* d_out, int out_size)
{
    (void)in_sizes; (void)n_in; (void)out_size;
    const float2* x1 = (const float2*)d_in[0];
    const float2* x2 = (const float2*)d_in[1];
    float* out = (float*)d_out;

    split_kernel<<<NPAIR / 256, 256>>>(x1, x2);

    cudaFuncSetAttribute(attn_kernel,
                         cudaFuncAttributeMaxDynamicSharedMemorySize, SMEM_BYTES);
    dim3 grid(SEQ / QT, BATCH);
    attn_kernel<<<grid, NT, SMEM_BYTES>>>(out);
}

// round 11
// speedup vs baseline: 1.1615x; 1.0036x over previous
#include <cuda_runtime.h>
#include <cuda_fp16.h>
#include <cstdint>
#include <cstddef>

#define BATCH 32
#define SEQ   2048
#define DIM   128
#define QT    64
#define KT    32
#define NT    128
#define NTILES (SEQ/KT)
#define SPLITS 2
#define TPS   (NTILES/SPLITS)    // tiles per split
#define HYST  6.0f

// smem: Q hi/lo 16KB each; K stages: (hi 8KB + lo 8KB) x 2
#define QH_OFF 0
#define QL_OFF 16384
#define KH_OFF(s) (32768 + (s)*16384)
#define KL_OFF(s) (40960 + (s)*16384)
static constexpr int SMEM_BYTES = 65536;

// pre-split fp16 hi/lo copies (u32 = packed half2), [b][seq][d]
#define NPAIR (BATCH*SEQ*DIM/2)
__device__ uint32_t qh_g[NPAIR];
__device__ uint32_t ql_g[NPAIR];
__device__ uint32_t kh_g[NPAIR];
__device__ uint32_t kl_g[NPAIR];

// split-K partials: unnormalized O + per-row (m, l)
__device__ float  opart_g[SPLITS * BATCH * SEQ * DIM];   // 64 MB
__device__ float2 ml_g[SPLITS * BATCH * SEQ];

#define MMA(C, A0, A1, A2, A3, B0, B1)                                  \
    asm volatile("mma.sync.aligned.m16n8k16.row.col.f32.f16.f16.f32 "   \
        "{%0,%1,%2,%3}, {%4,%5,%6,%7}, {%8,%9}, {%0,%1,%2,%3};"         \
        : "+f"(C[0]), "+f"(C[1]), "+f"(C[2]), "+f"(C[3])                \
        : "r"(A0), "r"(A1), "r"(A2), "r"(A3), "r"(B0), "r"(B1))

__device__ __forceinline__ void ldsm4(uint32_t& a, uint32_t& b, uint32_t& c,
                                      uint32_t& d, uint32_t addr)
{
    asm volatile("ldmatrix.sync.aligned.m8n8.x4.shared.b16 {%0,%1,%2,%3},[%4];"
                 : "=r"(a), "=r"(b), "=r"(c), "=r"(d) : "r"(addr));
}
__device__ __forceinline__ void ldsm4t(uint32_t& a, uint32_t& b, uint32_t& c,
                                       uint32_t& d, uint32_t addr)
{
    asm volatile("ldmatrix.sync.aligned.m8n8.x4.trans.shared.b16 {%0,%1,%2,%3},[%4];"
                 : "=r"(a), "=r"(b), "=r"(c), "=r"(d) : "r"(addr));
}
__device__ __forceinline__ void cp16(uint32_t dst, const void* src)
{
    asm volatile("cp.async.cg.shared.global [%0], [%1], 16;" :: "r"(dst), "l"(src));
}
#define CP_COMMIT()  asm volatile("cp.async.commit_group;")
#define CP_WAIT1()   asm volatile("cp.async.wait_group 1;")

// split (a,b) fp32 -> packed fp16 hi pair + lo pair (x = hi + lo)
__device__ __forceinline__ void split2(float a, float b, uint32_t& hi, uint32_t& lo)
{
    __half ha = __float2half_rn(a), hb = __float2half_rn(b);
    __half la = __float2half_rn(a - __half2float(ha));
    __half lb = __float2half_rn(b - __half2float(hb));
    __half2 H = __halves2half2(ha, hb);
    __half2 L = __halves2half2(la, lb);
    hi = *(uint32_t*)&H;
    lo = *(uint32_t*)&L;
}

// ---------------------------------------------------------------------------
// JAX threefry-2x32 (partitionable fold), key=(0,42). Verified R1-R10.
// ---------------------------------------------------------------------------
__device__ __forceinline__ uint32_t threefry_bits(uint32_t idx)
{
    uint32_t x0 = 0u;
    uint32_t x1 = idx + 42u;
    const uint32_t ks1 = 42u;
    const uint32_t ks2 = 0x1BD11BDAu ^ 42u;

#define TF_R4(a,b,c,d)                                          \
    x0 += x1; x1 = __funnelshift_l(x1, x1, (a)); x1 ^= x0;      \
    x0 += x1; x1 = __funnelshift_l(x1, x1, (b)); x1 ^= x0;      \
    x0 += x1; x1 = __funnelshift_l(x1, x1, (c)); x1 ^= x0;      \
    x0 += x1; x1 = __funnelshift_l(x1, x1, (d)); x1 ^= x0;

    TF_R4(13,15,26, 6)  x0 += ks1;  x1 += ks2 + 1u;
    TF_R4(17,29,16,24)  x0 += ks2;  x1 += 2u;
    TF_R4(13,15,26, 6)              x1 += ks1 + 3u;
    TF_R4(17,29,16,24)  x0 += ks1;  x1 += ks2 + 4u;
    TF_R4(13,15,26, 6)  x0 += ks2;  x1 += 5u;
#undef TF_R4
    return x0 ^ x1;
}

__global__ void split_kernel(const float2* __restrict__ x1,
                             const float2* __restrict__ x2)
{
    const float SCALE = 3.36358566f;   // 128**0.25 folded into Q
    int i = blockIdx.x * blockDim.x + threadIdx.x;
    float2 q = x1[i];
    float2 k = x2[i];
    uint32_t h, l;
    split2(q.x * SCALE, q.y * SCALE, h, l);
    qh_g[i] = h; ql_g[i] = l;
    split2(k.x, k.y, h, l);
    kh_g[i] = h; kl_g[i] = l;
}

// smem tile: rows x 256B (128 fp16), 16B chunks XOR-swizzled by row&7
template <int CHUNKS>
__device__ __forceinline__ void load_tile(uint32_t dstH, uint32_t dstL,
                                          const char* srcH, const char* srcL,
                                          int tid)
{
#pragma unroll
    for (int j = 0; j < CHUNKS / NT; ++j) {
        const int c   = tid + j * NT;
        const int row = c >> 4, ch = c & 15;
        const uint32_t off = row * 256 + ((ch ^ (row & 7)) << 4);
        cp16(dstH + off, srcH + c * 16);
        cp16(dstL + off, srcL + c * 16);
    }
}

// ---------------------------------------------------------------------------
// fp16 split flash attention + split-K(2). R8 body; CTA = (qtile, b, split).
// Each CTA streams TPS=32 k-tiles, writes unnormalized O + (m,l) partials.
// ---------------------------------------------------------------------------
__global__ void __launch_bounds__(NT, 3)
attn_kernel()
{
    extern __shared__ char smc[];
    const uint32_t smem = (uint32_t)__cvta_generic_to_shared(smc);

    const int b    = blockIdx.y;
    const int qt0  = blockIdx.x * QT;
    const int sp   = blockIdx.z;
    const int tid  = threadIdx.x;
    const int w    = tid >> 5;
    const int lane = tid & 31;
    const int g    = lane >> 2;
    const int p    = lane & 3;
    const int lane7 = lane & 7;
    const int sub   = lane >> 3;

    // ldmatrix addressing (row&7 == lane7 for all types):
    const int rA = lane7 + ((sub & 1) << 3);   // A-frag / trans-B row add
    const int cA = sub >> 1;                   // chunk add
    const int rB = lane7 + ((sub >> 1) << 3);  // B-frag (QK) row add
    const int cB = sub & 1;

    const char* qhb = (const char*)qh_g + (size_t)(b*SEQ + qt0) * 256;
    const char* qlb = (const char*)ql_g + (size_t)(b*SEQ + qt0) * 256;
    const char* khb = (const char*)kh_g + ((size_t)b*SEQ + (size_t)sp*TPS*KT) * 256;
    const char* klb = (const char*)kl_g + ((size_t)b*SEQ + (size_t)sp*TPS*KT) * 256;

    // prologue: Q + K tile 0 (group 0), K tile 1 (group 1)
    load_tile<QT*16>(smem + QH_OFF, smem + QL_OFF, qhb, qlb, tid);
    load_tile<KT*16>(smem + KH_OFF(0), smem + KL_OFF(0), khb, klb, tid);
    CP_COMMIT();
    load_tile<KT*16>(smem + KH_OFF(1), smem + KL_OFF(1), khb + KT*256, klb + KT*256, tid);
    CP_COMMIT();

    float o[16][4];
    float m0 = -1e30f, m1 = -1e30f, l0 = 0.f, l1 = 0.f;
#pragma unroll
    for (int nt = 0; nt < 16; ++nt)
#pragma unroll
        for (int j = 0; j < 4; ++j) o[nt][j] = 0.f;

    const uint32_t qrow = smem + QH_OFF + (w*16 + rA) * 256;
    const uint32_t rbase = (uint32_t)(b*SEQ + qt0 + w*16 + g) * (uint32_t)SEQ
                         + (uint32_t)(sp*TPS*KT) + 2*p;

    for (int t = 0; t < TPS; ++t) {
        CP_WAIT1();
        __syncthreads();
        const uint32_t kh0 = smem + KH_OFF(t & 1);

        // ---- S = Q K^T : 3-product fp16 MMA (KT=32 -> 4 n-tiles) ----
        float s[4][4];
#pragma unroll
        for (int nt = 0; nt < 4; ++nt)
#pragma unroll
            for (int j = 0; j < 4; ++j) s[nt][j] = 0.f;

#pragma unroll
        for (int kc = 0; kc < 8; ++kc) {
            const uint32_t aoff = ((2*kc + cA) ^ lane7) << 4;
            uint32_t qa0, qa1, qa2, qa3, la0, la1, la2, la3;
            ldsm4(qa0, qa1, qa2, qa3, qrow + aoff);
            ldsm4(la0, la1, la2, la3, qrow + aoff + (QL_OFF - QH_OFF));

            const uint32_t boff = ((2*kc + cB) ^ lane7) << 4;
#pragma unroll
            for (int n0g = 0; n0g < 2; ++n0g) {
                const uint32_t baddr = kh0 + (n0g*16 + rB) * 256 + boff;
                uint32_t kb0, kb1, kb2, kb3, lb0, lb1, lb2, lb3;
                ldsm4(kb0, kb1, kb2, kb3, baddr);
                ldsm4(lb0, lb1, lb2, lb3, baddr + 8192);
                const int nt = n0g * 2;
                MMA(s[nt],   qa0, qa1, qa2, qa3, kb0, kb1);
                MMA(s[nt+1], qa0, qa1, qa2, qa3, kb2, kb3);
                MMA(s[nt],   la0, la1, la2, la3, kb0, kb1);
                MMA(s[nt+1], la0, la1, la2, la3, kb2, kb3);
                MMA(s[nt],   qa0, qa1, qa2, qa3, lb0, lb1);
                MMA(s[nt+1], qa0, qa1, qa2, qa3, lb2, lb3);
            }
        }

        // ---- hysteresis online max ----
        float mx0 = -1e30f, mx1 = -1e30f;
#pragma unroll
        for (int nt = 0; nt < 4; ++nt) {
            mx0 = fmaxf(mx0, fmaxf(s[nt][0], s[nt][1]));
            mx1 = fmaxf(mx1, fmaxf(s[nt][2], s[nt][3]));
        }
        mx0 = fmaxf(mx0, __shfl_xor_sync(0xffffffffu, mx0, 1));
        mx0 = fmaxf(mx0, __shfl_xor_sync(0xffffffffu, mx0, 2));
        mx1 = fmaxf(mx1, __shfl_xor_sync(0xffffffffu, mx1, 1));
        mx1 = fmaxf(mx1, __shfl_xor_sync(0xffffffffu, mx1, 2));

        float c0 = 1.f, c1 = 1.f;
        int flag = 0;
        if (mx0 > m0 + HYST) { c0 = __expf(m0 - mx0); m0 = mx0; l0 *= c0; flag = 1; }
        if (mx1 > m1 + HYST) { c1 = __expf(m1 - mx1); m1 = mx1; l1 *= c1; flag = 1; }

        if (__ballot_sync(0xffffffffu, flag)) {   // rare: rescale O
#pragma unroll
            for (int nt = 0; nt < 16; ++nt) {
                o[nt][0] *= c0; o[nt][1] *= c0;
                o[nt][2] *= c1; o[nt][3] *= c1;
            }
        }

        // ---- gated exp + threefry dropout; pack P hi (fp16) ----
        const uint32_t rb0 = rbase + (uint32_t)(t*KT);
        const uint32_t rb1 = rb0 + 8u * (uint32_t)SEQ;

        uint32_t ph[4][2];
#pragma unroll
        for (int nt = 0; nt < 4; ++nt) {
            float pm[4];
#pragma unroll
            for (int j = 0; j < 4; ++j) {
                const bool hi8 = (j >= 2);
                const float dlt = s[nt][j] - (hi8 ? m1 : m0);
                float v = 0.f;
                if (dlt > -18.42f) {   // p/pmax >= ~1e-8: term matters
                    const float e = __expf(dlt);
                    if (hi8) l1 += e; else l0 += e;
                    const uint32_t idx = (hi8 ? rb1 : rb0) + nt*8 + (j & 1);
                    const uint32_t bits = threefry_bits(idx);
                    const float u = __uint_as_float((bits >> 9) | 0x3f800000u) - 1.0f;
                    v = (u < 0.9f) ? e : 0.f;
                }
                pm[j] = v;
            }
            __half2 h01 = __floats2half2_rn(pm[0], pm[1]);
            __half2 h23 = __floats2half2_rn(pm[2], pm[3]);
            ph[nt][0] = *(uint32_t*)&h01;
            ph[nt][1] = *(uint32_t*)&h23;
        }

        // ---- O += P~ V : 1 product (Ph*Vh), V == K tile, trans ----
#pragma unroll
        for (int kc2 = 0; kc2 < 2; ++kc2) {
            const uint32_t pa0 = ph[2*kc2][0],   pa1 = ph[2*kc2][1];
            const uint32_t pa2 = ph[2*kc2+1][0], pa3 = ph[2*kc2+1][1];
            const uint32_t trow = kh0 + (kc2*16 + rA) * 256;
#pragma unroll
            for (int dcp = 0; dcp < 8; ++dcp) {
                const uint32_t toff = ((2*dcp + cA) ^ lane7) << 4;
                uint32_t vb0, vb1, vb2, vb3;
                ldsm4t(vb0, vb1, vb2, vb3, trow + toff);
                const int nt = dcp * 2;
                MMA(o[nt],   pa0, pa1, pa2, pa3, vb0, vb1);
                MMA(o[nt+1], pa0, pa1, pa2, pa3, vb2, vb3);
            }
        }

        __syncthreads();
        if (t + 2 < TPS)
            load_tile<KT*16>(smem + KH_OFF(t & 1), smem + KL_OFF(t & 1),
                             khb + (size_t)(t + 2) * KT * 256,
                             klb + (size_t)(t + 2) * KT * 256, tid);
        CP_COMMIT();   // empty groups near the tail keep wait_group semantics
    }

    // ---- partial epilogue: reduce l, store (m,l) + unnormalized O ----
    l0 += __shfl_xor_sync(0xffffffffu, l0, 1);
    l0 += __shfl_xor_sync(0xffffffffu, l0, 2);
    l1 += __shfl_xor_sync(0xffffffffu, l1, 1);
    l1 += __shfl_xor_sync(0xffffffffu, l1, 2);

    const int row0 = qt0 + w*16 + g;
    const size_t rbw = (size_t)sp * BATCH * SEQ + (size_t)b * SEQ + row0;
    if (p == 0) {
        ml_g[rbw]     = make_float2(m0, l0);
        ml_g[rbw + 8] = make_float2(m1, l1);
    }

    float2* op0 = (float2*)(opart_g + rbw * DIM);
    float2* op1 = (float2*)(opart_g + (rbw + 8) * DIM);
#pragma unroll
    for (int nt = 0; nt < 16; ++nt) {
        float2 v0, v1;
        v0.x = o[nt][0]; v0.y = o[nt][1];
        v1.x = o[nt][2]; v1.y = o[nt][3];
        op0[nt*4 + p] = v0;
        op1[nt*4 + p] = v1;
    }
}

// ---------------------------------------------------------------------------
// Merge: out = (e^{m0-M} O0 + e^{m1-M} O1) / ((e^{m0-M} l0 + e^{m1-M} l1) 0.9)
// ---------------------------------------------------------------------------
__global__ void merge_kernel(float4* __restrict__ out)
{
    const int i   = blockIdx.x * blockDim.x + threadIdx.x;   // float4 index
    const int row = i >> 5;                                  // DIM/4 = 32
    const float2 ml0 = ml_g[row];
    const float2 ml1 = ml_g[BATCH*SEQ + row];
    const float M  = fmaxf(ml0.x, ml1.x);
    const float c0 = __expf(ml0.x - M);
    const float c1 = __expf(ml1.x - M);
    const float inv = 1.0f / ((ml0.y * c0 + ml1.y * c1) * 0.9f);
    const float4 a = ((const float4*)opart_g)[i];
    const float4 b = ((const float4*)opart_g)[BATCH*SEQ*(DIM/4) + i];
    float4 r;
    r.x = (a.x*c0 + b.x*c1) * inv;
    r.y = (a.y*c0 + b.y*c1) * inv;
    r.z = (a.z*c0 + b.z*c1) * inv;
    r.w = (a.w*c0 + b.w*c1) * inv;
    out[i] = r;
}

extern "C" void kernel_launch(void* const* d_in, const int* in_sizes, int n_in,
                              void* d_out, int out_size)
{
    (void)in_sizes; (void)n_in; (void)out_size;
    const float2* x1 = (const float2*)d_in[0];
    const float2* x2 = (const float2*)d_in[1];
    float4* out = (float4*)d_out;

    split_kernel<<<NPAIR / 256, 256>>>(x1, x2);

    cudaFuncSetAttribute(attn_kernel,
                         cudaFuncAttributeMaxDynamicSharedMemorySize, SMEM_BYTES);
    dim3 grid(SEQ / QT, BATCH, SPLITS);
    attn_kernel<<<grid, NT, SMEM_BYTES>>>();

    merge_kernel<<<BATCH*SEQ*(DIM/4) / 256, 256>>>(out);
}